// round 12
// baseline (speedup 1.0000x reference)
#include <cuda_runtime.h>
#include <cuda_bf16.h>
#include <mma.h>
#include <cstdint>

using namespace nvcuda;

#define BB 4
#define NN 4096
#define DD 256

typedef __nv_bfloat16 bf16;

__device__ bf16 g_valh[BB * NN * DD];
__device__ bf16 g_vall[BB * NN * DD];
__device__ bf16 g_pvh[BB * NN * DD];   // [b][n][e]
__device__ bf16 g_pvl[BB * NN * DD];
__device__ bf16 g_wvh[DD * DD];        // [d][e]
__device__ bf16 g_wvl[DD * DD];

// ---------------- split kernels ----------------
__global__ __launch_bounds__(256) void split_val(const float* __restrict__ val) {
    int i = (blockIdx.x * 256 + threadIdx.x) * 4;
    float4 v = *reinterpret_cast<const float4*>(val + i);
    __nv_bfloat162 h0 = __floats2bfloat162_rn(v.x, v.y);
    __nv_bfloat162 h1 = __floats2bfloat162_rn(v.z, v.w);
    __nv_bfloat162 l0 = __floats2bfloat162_rn(v.x - __bfloat162float(h0.x),
                                              v.y - __bfloat162float(h0.y));
    __nv_bfloat162 l1 = __floats2bfloat162_rn(v.z - __bfloat162float(h1.x),
                                              v.w - __bfloat162float(h1.y));
    *reinterpret_cast<__nv_bfloat162*>(g_valh + i)     = h0;
    *reinterpret_cast<__nv_bfloat162*>(g_valh + i + 2) = h1;
    *reinterpret_cast<__nv_bfloat162*>(g_vall + i)     = l0;
    *reinterpret_cast<__nv_bfloat162*>(g_vall + i + 2) = l1;
}

__global__ __launch_bounds__(256) void split_wv(const float* __restrict__ Wv) {
    int i = blockIdx.x * 256 + threadIdx.x;
    float w = Wv[i];
    bf16 h = __float2bfloat16(w);
    g_wvh[i] = h;
    g_wvl[i] = __float2bfloat16(w - __bfloat162float(h));
}

// ---------------- pv kernel: pv[n][e] = sum_d val[n][d] * Wv[d][e] ----------------
// CTA: 64 rows, 512 threads (16 warps, 4x4 warp grid). smem: A(64x264 h/l) + Wv chunk.
#define LDA 264
__global__ __launch_bounds__(512, 1) void pv_kernel() {
    extern __shared__ char sm[];
    bf16* Ah = reinterpret_cast<bf16*>(sm);                    // 64 x 264
    bf16* Al = reinterpret_cast<bf16*>(sm + 33792);
    bf16* Wh = reinterpret_cast<bf16*>(sm + 67584);            // 64 x 264
    bf16* Wl = reinterpret_cast<bf16*>(sm + 101376);
    float* stage = reinterpret_cast<float*>(sm + 67584);       // alias: 64 x 264 fp32

    const int t = threadIdx.x;
    const int n0 = blockIdx.x * 64;
    const int wid = t >> 5;
    const int wm = wid & 3, wn = wid >> 2;

    // load A = val rows [n0, n0+64), all 256 d (hi/lo)
#pragma unroll
    for (int it = 0; it < 4; it++) {
        int idx = it * 512 + t;
        int r = idx >> 5, c = idx & 31;
        *reinterpret_cast<uint4*>(Ah + r * LDA + c * 8) =
            *reinterpret_cast<const uint4*>(g_valh + (size_t)(n0 + r) * DD + c * 8);
        *reinterpret_cast<uint4*>(Al + r * LDA + c * 8) =
            *reinterpret_cast<const uint4*>(g_vall + (size_t)(n0 + r) * DD + c * 8);
    }

    wmma::fragment<wmma::accumulator, 16, 16, 16, float> acc[4];
#pragma unroll
    for (int e = 0; e < 4; e++) wmma::fill_fragment(acc[e], 0.f);

    for (int kc = 0; kc < 4; kc++) {
        __syncthreads();
        // load Wv chunk [kk..kk+64) x 256 (hi/lo)
#pragma unroll
        for (int it = 0; it < 4; it++) {
            int idx = it * 512 + t;
            int r = idx >> 5, c = idx & 31;
            *reinterpret_cast<uint4*>(Wh + r * LDA + c * 8) =
                *reinterpret_cast<const uint4*>(g_wvh + (kc * 64 + r) * DD + c * 8);
            *reinterpret_cast<uint4*>(Wl + r * LDA + c * 8) =
                *reinterpret_cast<const uint4*>(g_wvl + (kc * 64 + r) * DD + c * 8);
        }
        __syncthreads();
#pragma unroll
        for (int ks = 0; ks < 4; ks++) {
            wmma::fragment<wmma::matrix_a, 16, 16, 16, bf16, wmma::row_major> ah, al;
            wmma::load_matrix_sync(ah, Ah + wm * 16 * LDA + kc * 64 + ks * 16, LDA);
            wmma::load_matrix_sync(al, Al + wm * 16 * LDA + kc * 64 + ks * 16, LDA);
#pragma unroll
            for (int e = 0; e < 4; e++) {
                wmma::fragment<wmma::matrix_b, 16, 16, 16, bf16, wmma::row_major> bh, bl;
                wmma::load_matrix_sync(bh, Wh + ks * 16 * LDA + wn * 64 + e * 16, LDA);
                wmma::load_matrix_sync(bl, Wl + ks * 16 * LDA + wn * 64 + e * 16, LDA);
                wmma::mma_sync(acc[e], ah, bh, acc[e]);
                wmma::mma_sync(acc[e], ah, bl, acc[e]);
                wmma::mma_sync(acc[e], al, bh, acc[e]);
            }
        }
    }
    __syncthreads();
#pragma unroll
    for (int e = 0; e < 4; e++)
        wmma::store_matrix_sync(stage + wm * 16 * LDA + wn * 64 + e * 16, acc[e],
                                LDA, wmma::mem_row_major);
    __syncthreads();
    // split to bf16 hi/lo and store
    const int r = t >> 3, grp = t & 7;
#pragma unroll
    for (int j = 0; j < 32; j++) {
        int e = grp * 32 + j;
        float f = stage[r * LDA + e];
        bf16 h = __float2bfloat16(f);
        g_pvh[(size_t)(n0 + r) * DD + e] = h;
        g_pvl[(size_t)(n0 + r) * DD + e] = __float2bfloat16(f - __bfloat162float(h));
    }
}

// ---------------- fused propagation ----------------
// CTA: 64 q-rows, 512 threads (16 warps). Key tiles of 128.
// smem: Q(64x264 h/l) 67.5KB + P(64x136 h/l) 34KB + state 512B + buf 36KB
#define LDK 72
#define LDP 136
#define LDS_ 132
#define OFF_QL  33792
#define OFF_PH  67584
#define OFF_PL  84992
#define OFF_ST  102400
#define OFF_BUF 102912

__global__ __launch_bounds__(512, 1) void prop_kernel(const float* __restrict__ state,
                                                      float* __restrict__ out_ds,
                                                      float* __restrict__ out_dv) {
    extern __shared__ char sm[];
    bf16* Qh = reinterpret_cast<bf16*>(sm);
    bf16* Ql = reinterpret_cast<bf16*>(sm + OFF_QL);
    bf16* Ph = reinterpret_cast<bf16*>(sm + OFF_PH);
    bf16* Pl = reinterpret_cast<bf16*>(sm + OFF_PL);
    float* state_s = reinterpret_cast<float*>(sm + OFF_ST);
    bf16* Kh = reinterpret_cast<bf16*>(sm + OFF_BUF);            // 128 x 72
    bf16* Kl = reinterpret_cast<bf16*>(sm + OFF_BUF + 18432);
    bf16* Vh = reinterpret_cast<bf16*>(sm + OFF_BUF);            // 32 x 264 (pv chunk)
    bf16* Vl = reinterpret_cast<bf16*>(sm + OFF_BUF + 16896);
    float* Sbuf = reinterpret_cast<float*>(sm + OFF_BUF);        // 64 x 132 fp32

    const int t = threadIdx.x;
    const int b = blockIdx.x >> 6;
    const int n0q = (blockIdx.x & 63) * 64;
    const int wid = t >> 5;
    const int wm = wid & 3, wn = wid >> 2;
    const bf16* vh = g_valh + (size_t)b * NN * DD;
    const bf16* vl = g_vall + (size_t)b * NN * DD;
    const bf16* pvh = g_pvh + (size_t)b * NN * DD;
    const bf16* pvl = g_pvl + (size_t)b * NN * DD;

    // persistent Q load
#pragma unroll
    for (int it = 0; it < 4; it++) {
        int idx = it * 512 + t;
        int r = idx >> 5, c = idx & 31;
        *reinterpret_cast<uint4*>(Qh + r * LDA + c * 8) =
            *reinterpret_cast<const uint4*>(vh + (size_t)(n0q + r) * DD + c * 8);
        *reinterpret_cast<uint4*>(Ql + r * LDA + c * 8) =
            *reinterpret_cast<const uint4*>(vl + (size_t)(n0q + r) * DD + c * 8);
    }

    wmma::fragment<wmma::accumulator, 16, 16, 16, float> dv[4];
#pragma unroll
    for (int e = 0; e < 4; e++) wmma::fill_fragment(dv[e], 0.f);
    float dsac = 0.f;

    for (int mt = 0; mt < 32; mt++) {
        const int m0 = mt * 128;
        wmma::fragment<wmma::accumulator, 16, 16, 16, float> cS[2];
        wmma::fill_fragment(cS[0], 0.f);
        wmma::fill_fragment(cS[1], 0.f);

        // ---- GEMM1: S = Q . K^T over 4 chunks of K=64 ----
        for (int kc = 0; kc < 4; kc++) {
            __syncthreads();
#pragma unroll
            for (int it = 0; it < 2; it++) {
                int idx = it * 512 + t;
                int r = idx >> 3, c = idx & 7;
                *reinterpret_cast<uint4*>(Kh + r * LDK + c * 8) =
                    *reinterpret_cast<const uint4*>(vh + (size_t)(m0 + r) * DD + kc * 64 + c * 8);
                *reinterpret_cast<uint4*>(Kl + r * LDK + c * 8) =
                    *reinterpret_cast<const uint4*>(vl + (size_t)(m0 + r) * DD + kc * 64 + c * 8);
            }
            if (kc == 0 && t < 128) state_s[t] = state[b * NN + m0 + t];
            __syncthreads();
#pragma unroll
            for (int ks = 0; ks < 4; ks++) {
                wmma::fragment<wmma::matrix_a, 16, 16, 16, bf16, wmma::row_major> ah, al;
                wmma::load_matrix_sync(ah, Qh + wm * 16 * LDA + kc * 64 + ks * 16, LDA);
                wmma::load_matrix_sync(al, Ql + wm * 16 * LDA + kc * 64 + ks * 16, LDA);
#pragma unroll
                for (int nn = 0; nn < 2; nn++) {
                    wmma::fragment<wmma::matrix_b, 16, 16, 16, bf16, wmma::col_major> bh, bl;
                    wmma::load_matrix_sync(bh, Kh + (wn * 32 + nn * 16) * LDK + ks * 16, LDK);
                    wmma::load_matrix_sync(bl, Kl + (wn * 32 + nn * 16) * LDK + ks * 16, LDK);
                    wmma::mma_sync(cS[nn], ah, bh, cS[nn]);
                    wmma::mma_sync(cS[nn], ah, bl, cS[nn]);
                    wmma::mma_sync(cS[nn], al, bh, cS[nn]);
                }
            }
        }
        __syncthreads();
        wmma::store_matrix_sync(Sbuf + wm * 16 * LDS_ + wn * 32 + 0,  cS[0], LDS_, wmma::mem_row_major);
        wmma::store_matrix_sync(Sbuf + wm * 16 * LDS_ + wn * 32 + 16, cS[1], LDS_, wmma::mem_row_major);
        __syncthreads();

        // ---- softsign + ds + split P to bf16 hi/lo ----
        {
            const int r = t >> 3, grp = t & 7;
#pragma unroll
            for (int j = 0; j < 16; j++) {
                int col = grp * 16 + j;
                float s = Sbuf[r * LDS_ + col];
                float p = s / (1.f + fabsf(s));
                dsac += p * state_s[col];
                bf16 h = __float2bfloat16(p);
                Ph[r * LDP + col] = h;
                Pl[r * LDP + col] = __float2bfloat16(p - __bfloat162float(h));
            }
        }

        // ---- GEMM2: dv += P . pv over 4 chunks of 32 keys ----
        for (int kc = 0; kc < 4; kc++) {
            __syncthreads();
#pragma unroll
            for (int it = 0; it < 2; it++) {
                int idx = it * 512 + t;
                int r = idx >> 5, c = idx & 31;
                *reinterpret_cast<uint4*>(Vh + r * LDA + c * 8) =
                    *reinterpret_cast<const uint4*>(pvh + (size_t)(m0 + kc * 32 + r) * DD + c * 8);
                *reinterpret_cast<uint4*>(Vl + r * LDA + c * 8) =
                    *reinterpret_cast<const uint4*>(pvl + (size_t)(m0 + kc * 32 + r) * DD + c * 8);
            }
            __syncthreads();
#pragma unroll
            for (int ks = 0; ks < 2; ks++) {
                wmma::fragment<wmma::matrix_a, 16, 16, 16, bf16, wmma::row_major> ah, al;
                wmma::load_matrix_sync(ah, Ph + wm * 16 * LDP + kc * 32 + ks * 16, LDP);
                wmma::load_matrix_sync(al, Pl + wm * 16 * LDP + kc * 32 + ks * 16, LDP);
#pragma unroll
                for (int e = 0; e < 4; e++) {
                    wmma::fragment<wmma::matrix_b, 16, 16, 16, bf16, wmma::row_major> bh, bl;
                    wmma::load_matrix_sync(bh, Vh + ks * 16 * LDA + wn * 64 + e * 16, LDA);
                    wmma::load_matrix_sync(bl, Vl + ks * 16 * LDA + wn * 64 + e * 16, LDA);
                    wmma::mma_sync(dv[e], ah, bh, dv[e]);
                    wmma::mma_sync(dv[e], ah, bl, dv[e]);
                    wmma::mma_sync(dv[e], al, bh, dv[e]);
                }
            }
        }
    }

    // ---- outputs ----
#pragma unroll
    for (int e = 0; e < 4; e++)
        wmma::store_matrix_sync(out_dv + ((size_t)b * NN + n0q + wm * 16) * DD + wn * 64 + e * 16,
                                dv[e], DD, wmma::mem_row_major);
    dsac += __shfl_xor_sync(0xffffffffu, dsac, 1);
    dsac += __shfl_xor_sync(0xffffffffu, dsac, 2);
    dsac += __shfl_xor_sync(0xffffffffu, dsac, 4);
    if ((t & 7) == 0) out_ds[b * NN + n0q + (t >> 3)] = dsac;
}

// ---------------------------------------------------------------------------
extern "C" void kernel_launch(void* const* d_in, const int* in_sizes, int n_in,
                              void* d_out, int out_size) {
    const float* val = nullptr;
    const float* state = nullptr;
    const float* Wv = nullptr;
    for (int i = 0; i < n_in; i++) {
        if (in_sizes[i] == BB * NN * DD) val = (const float*)d_in[i];
        else if (in_sizes[i] == BB * NN) state = (const float*)d_in[i];
        else if (in_sizes[i] == DD * DD) Wv = (const float*)d_in[i];
    }
    float* out    = (float*)d_out;
    float* out_ds = out;
    float* out_dv = out + BB * NN;

    cudaFuncSetAttribute(pv_kernel, cudaFuncAttributeMaxDynamicSharedMemorySize, 135168);
    cudaFuncSetAttribute(prop_kernel, cudaFuncAttributeMaxDynamicSharedMemorySize, 139776);

    split_val<<<BB * NN * DD / 1024, 256>>>(val);
    split_wv<<<DD, 256>>>(Wv);
    pv_kernel<<<BB * NN / 64, 512, 135168>>>();
    prop_kernel<<<BB * (NN / 64), 512, 139776>>>(state, out_ds, out_dv);
}

// round 13
// speedup vs baseline: 1.1962x; 1.1962x over previous
#include <cuda_runtime.h>
#include <cuda_bf16.h>
#include <mma.h>
#include <cstdint>

using namespace nvcuda;

#define BB 4
#define NN 4096
#define DD 256

typedef __nv_bfloat16 bf16;

__device__ bf16 g_valh[BB * NN * DD];
__device__ bf16 g_vall[BB * NN * DD];
__device__ bf16 g_pvh[BB * NN * DD];   // [b][n][e]
__device__ bf16 g_pvl[BB * NN * DD];
__device__ bf16 g_wvh[DD * DD];        // [d][e]
__device__ bf16 g_wvl[DD * DD];

// ---------------- cp.async helpers ----------------
#define CPA(dst, src) \
    asm volatile("cp.async.cg.shared.global [%0], [%1], 16;" :: "r"(dst), "l"(src))
#define CPC() asm volatile("cp.async.commit_group;" ::: "memory")
#define CPW1() asm volatile("cp.async.wait_group 1;" ::: "memory")
#define CPW0() asm volatile("cp.async.wait_group 0;" ::: "memory")

__device__ __forceinline__ uint32_t sptr(const void* p) {
    return (uint32_t)__cvta_generic_to_shared(p);
}

// ---------------- split kernels ----------------
__global__ __launch_bounds__(256) void split_val(const float* __restrict__ val) {
    int i = (blockIdx.x * 256 + threadIdx.x) * 4;
    float4 v = *reinterpret_cast<const float4*>(val + i);
    __nv_bfloat162 h0 = __floats2bfloat162_rn(v.x, v.y);
    __nv_bfloat162 h1 = __floats2bfloat162_rn(v.z, v.w);
    __nv_bfloat162 l0 = __floats2bfloat162_rn(v.x - __bfloat162float(h0.x),
                                              v.y - __bfloat162float(h0.y));
    __nv_bfloat162 l1 = __floats2bfloat162_rn(v.z - __bfloat162float(h1.x),
                                              v.w - __bfloat162float(h1.y));
    *reinterpret_cast<__nv_bfloat162*>(g_valh + i)     = h0;
    *reinterpret_cast<__nv_bfloat162*>(g_valh + i + 2) = h1;
    *reinterpret_cast<__nv_bfloat162*>(g_vall + i)     = l0;
    *reinterpret_cast<__nv_bfloat162*>(g_vall + i + 2) = l1;
}

__global__ __launch_bounds__(256) void split_wv(const float* __restrict__ Wv) {
    int i = blockIdx.x * 256 + threadIdx.x;
    float w = Wv[i];
    bf16 h = __float2bfloat16(w);
    g_wvh[i] = h;
    g_wvl[i] = __float2bfloat16(w - __bfloat162float(h));
}

// ---------------- pv kernel: pv[n][e] = sum_d val[n][d] * Wv[d][e] ----------------
// 64 rows per CTA, 512 threads (4x4 warp grid), double-buffered Wv chunks.
#define LDA 264
#define PV_B0 67584
#define PV_B1 135168
__global__ __launch_bounds__(512, 1) void pv_kernel() {
    extern __shared__ char sm[];
    bf16* Ah = reinterpret_cast<bf16*>(sm);                    // 64 x 264
    bf16* Al = reinterpret_cast<bf16*>(sm + 33792);
    float* stage = reinterpret_cast<float*>(sm + PV_B0);       // alias on buffers

    const int t = threadIdx.x;
    const int n0 = blockIdx.x * 64;
    const int wid = t >> 5;
    const int wm = wid & 3, wn = wid >> 2;

    // prologue: cp.async A (hi/lo) + W chunk 0 into B0, one group
    {
        const int r = t >> 3, c = (t & 7) * 8;   // 64 rows x 64 cols per pass
#pragma unroll
        for (int it = 0; it < 4; it++) {
            int cc = c + it * 64;
            CPA(sptr(Ah + r * LDA + cc), g_valh + (size_t)(n0 + r) * DD + cc);
            CPA(sptr(Al + r * LDA + cc), g_vall + (size_t)(n0 + r) * DD + cc);
            CPA(sptr(sm + PV_B0) + (uint32_t)(r * LDA + cc) * 2,
                g_wvh + (size_t)r * DD + cc);
            CPA(sptr(sm + PV_B0 + 33792) + (uint32_t)(r * LDA + cc) * 2,
                g_wvl + (size_t)r * DD + cc);
        }
        CPC();
    }

    wmma::fragment<wmma::accumulator, 16, 16, 16, float> acc[4];
#pragma unroll
    for (int e = 0; e < 4; e++) wmma::fill_fragment(acc[e], 0.f);

    for (int kc = 0; kc < 4; kc++) {
        char* buf = sm + ((kc & 1) ? PV_B1 : PV_B0);
        // issue next W chunk
        if (kc < 3) {
            char* nb = sm + (((kc + 1) & 1) ? PV_B1 : PV_B0);
            const int r = t >> 3, c = (t & 7) * 8;
#pragma unroll
            for (int it = 0; it < 4; it++) {
                int cc = c + it * 64;
                CPA(sptr(nb) + (uint32_t)(r * LDA + cc) * 2,
                    g_wvh + (size_t)((kc + 1) * 64 + r) * DD + cc);
                CPA(sptr(nb + 33792) + (uint32_t)(r * LDA + cc) * 2,
                    g_wvl + (size_t)((kc + 1) * 64 + r) * DD + cc);
            }
        }
        CPC();
        CPW1();
        __syncthreads();
        bf16* Wh = reinterpret_cast<bf16*>(buf);
        bf16* Wl = reinterpret_cast<bf16*>(buf + 33792);
#pragma unroll
        for (int ks = 0; ks < 4; ks++) {
            wmma::fragment<wmma::matrix_a, 16, 16, 16, bf16, wmma::row_major> ah, al;
            wmma::load_matrix_sync(ah, Ah + wm * 16 * LDA + kc * 64 + ks * 16, LDA);
            wmma::load_matrix_sync(al, Al + wm * 16 * LDA + kc * 64 + ks * 16, LDA);
#pragma unroll
            for (int e = 0; e < 4; e++) {
                wmma::fragment<wmma::matrix_b, 16, 16, 16, bf16, wmma::row_major> bh, bl;
                wmma::load_matrix_sync(bh, Wh + ks * 16 * LDA + wn * 64 + e * 16, LDA);
                wmma::load_matrix_sync(bl, Wl + ks * 16 * LDA + wn * 64 + e * 16, LDA);
                wmma::mma_sync(acc[e], ah, bh, acc[e]);
                wmma::mma_sync(acc[e], ah, bl, acc[e]);
                wmma::mma_sync(acc[e], al, bh, acc[e]);
            }
        }
        __syncthreads();
    }
#pragma unroll
    for (int e = 0; e < 4; e++)
        wmma::store_matrix_sync(stage + wm * 16 * LDA + wn * 64 + e * 16, acc[e],
                                LDA, wmma::mem_row_major);
    __syncthreads();
    const int r = t >> 3, grp = t & 7;
#pragma unroll
    for (int j = 0; j < 32; j++) {
        int e = grp * 32 + j;
        float f = stage[r * LDA + e];
        bf16 h = __float2bfloat16(f);
        g_pvh[(size_t)(n0 + r) * DD + e] = h;
        g_pvl[(size_t)(n0 + r) * DD + e] = __float2bfloat16(f - __bfloat162float(h));
    }
}

// ---------------- fused propagation ----------------
// 64 q-rows per CTA, 512 threads. Key tiles of 128 keys, 8 chunks/tile
// (4 K chunks 128x64 + 4 V chunks 32x256), double-buffered via cp.async.
#define LDK 72
#define LDP 136
#define LDS_ 132
#define OFF_QL  33792
#define OFF_PH  67584
#define OFF_PL  84992
#define OFF_ST  102400
#define OFF_S   102912
#define OFF_B0  136704
#define OFF_B1  173568
#define BUF_LO  18432

__global__ __launch_bounds__(512, 1) void prop_kernel(const float* __restrict__ state,
                                                      float* __restrict__ out_ds,
                                                      float* __restrict__ out_dv) {
    extern __shared__ char sm[];
    bf16* Qh = reinterpret_cast<bf16*>(sm);
    bf16* Ql = reinterpret_cast<bf16*>(sm + OFF_QL);
    bf16* Ph = reinterpret_cast<bf16*>(sm + OFF_PH);
    bf16* Pl = reinterpret_cast<bf16*>(sm + OFF_PL);
    float* state_s = reinterpret_cast<float*>(sm + OFF_ST);
    float* Sbuf = reinterpret_cast<float*>(sm + OFF_S);

    const int t = threadIdx.x;
    const int b = blockIdx.x >> 6;
    const int n0q = (blockIdx.x & 63) * 64;
    const int wid = t >> 5;
    const int wm1 = wid & 3, wn1 = wid >> 2;   // GEMM1: 16x32 tiles
    const int wm2 = wid & 1, wn2 = wid >> 1;   // GEMM2: 32x32 tiles
    const bf16* vh = g_valh + (size_t)b * NN * DD;
    const bf16* vl = g_vall + (size_t)b * NN * DD;
    const bf16* pvh = g_pvh + (size_t)b * NN * DD;
    const bf16* pvl = g_pvl + (size_t)b * NN * DD;

    // chunk issue helper (as lambda): cc 0..3 = K chunk, 4..7 = V chunk
    auto issue = [&](int m0, int cc) {
        char* buf = sm + ((cc & 1) ? OFF_B1 : OFF_B0);
        if (cc < 4) {
            const int r = t >> 3, c = (t & 7) * 8;   // 64 rows x 64 cols/pass
            const int kk = cc * 64;
#pragma unroll
            for (int it = 0; it < 2; it++) {
                int rr = r + it * 64;
                CPA(sptr(buf) + (uint32_t)(rr * LDK + c) * 2,
                    vh + (size_t)(m0 + rr) * DD + kk + c);
                CPA(sptr(buf + BUF_LO) + (uint32_t)(rr * LDK + c) * 2,
                    vl + (size_t)(m0 + rr) * DD + kk + c);
            }
        } else {
            const int r = t >> 5, c = (t & 31) * 8;  // 16 rows x 256 cols/pass
            const int r0 = (cc - 4) * 32;
#pragma unroll
            for (int it = 0; it < 2; it++) {
                int rr = r + it * 16;
                CPA(sptr(buf) + (uint32_t)(rr * LDA + c) * 2,
                    pvh + (size_t)(m0 + r0 + rr) * DD + c);
                CPA(sptr(buf + BUF_LO) + (uint32_t)(rr * LDA + c) * 2,
                    pvl + (size_t)(m0 + r0 + rr) * DD + c);
            }
        }
    };

    // prologue: issue tile0 K0; plain-load Q (overlaps)
    issue(0, 0);
    CPC();
#pragma unroll
    for (int it = 0; it < 4; it++) {
        int idx = it * 512 + t;
        int r = idx >> 5, c = idx & 31;
        *reinterpret_cast<uint4*>(Qh + r * LDA + c * 8) =
            *reinterpret_cast<const uint4*>(vh + (size_t)(n0q + r) * DD + c * 8);
        *reinterpret_cast<uint4*>(Ql + r * LDA + c * 8) =
            *reinterpret_cast<const uint4*>(vl + (size_t)(n0q + r) * DD + c * 8);
    }

    wmma::fragment<wmma::accumulator, 16, 16, 16, float> dv[2][2];
#pragma unroll
    for (int i = 0; i < 2; i++)
#pragma unroll
        for (int j = 0; j < 2; j++) wmma::fill_fragment(dv[i][j], 0.f);
    float dsac = 0.f;

    for (int mt = 0; mt < 32; mt++) {
        const int m0 = mt * 128;
        wmma::fragment<wmma::accumulator, 16, 16, 16, float> cS[2];
        wmma::fill_fragment(cS[0], 0.f);
        wmma::fill_fragment(cS[1], 0.f);

        // ---- GEMM1: K chunks 0..3 ----
        for (int cc = 0; cc < 4; cc++) {
            issue(m0, cc + 1);      // cc=3 issues V chunk 0
            CPC();
            if (cc == 0 && t < 128) state_s[t] = state[b * NN + m0 + t];
            CPW1();
            __syncthreads();
            char* buf = sm + ((cc & 1) ? OFF_B1 : OFF_B0);
            bf16* Kh = reinterpret_cast<bf16*>(buf);
            bf16* Kl = reinterpret_cast<bf16*>(buf + BUF_LO);
#pragma unroll
            for (int ks = 0; ks < 4; ks++) {
                wmma::fragment<wmma::matrix_a, 16, 16, 16, bf16, wmma::row_major> ah, al;
                wmma::load_matrix_sync(ah, Qh + wm1 * 16 * LDA + cc * 64 + ks * 16, LDA);
                wmma::load_matrix_sync(al, Ql + wm1 * 16 * LDA + cc * 64 + ks * 16, LDA);
#pragma unroll
                for (int nn = 0; nn < 2; nn++) {
                    wmma::fragment<wmma::matrix_b, 16, 16, 16, bf16, wmma::col_major> bh, bl;
                    wmma::load_matrix_sync(bh, Kh + (wn1 * 32 + nn * 16) * LDK + ks * 16, LDK);
                    wmma::load_matrix_sync(bl, Kl + (wn1 * 32 + nn * 16) * LDK + ks * 16, LDK);
                    wmma::mma_sync(cS[nn], ah, bh, cS[nn]);
                    wmma::mma_sync(cS[nn], ah, bl, cS[nn]);
                    wmma::mma_sync(cS[nn], al, bh, cS[nn]);
                }
            }
            __syncthreads();
        }

        // ---- softsign + ds + P split (V0 in flight) ----
        wmma::store_matrix_sync(Sbuf + wm1 * 16 * LDS_ + wn1 * 32 + 0,  cS[0], LDS_, wmma::mem_row_major);
        wmma::store_matrix_sync(Sbuf + wm1 * 16 * LDS_ + wn1 * 32 + 16, cS[1], LDS_, wmma::mem_row_major);
        __syncthreads();
        {
            const int r = t >> 3, grp = t & 7;
#pragma unroll
            for (int j = 0; j < 16; j++) {
                int col = grp * 16 + j;
                float s = Sbuf[r * LDS_ + col];
                float p = s / (1.f + fabsf(s));
                dsac += p * state_s[col];
                bf16 h = __float2bfloat16(p);
                Ph[r * LDP + col] = h;
                Pl[r * LDP + col] = __float2bfloat16(p - __bfloat162float(h));
            }
        }

        // ---- GEMM2: V chunks 4..7 ----
        for (int cc = 4; cc < 8; cc++) {
            if (cc < 7) issue(m0, cc + 1);
            else if (mt < 31) issue(m0 + 128, 0);   // next tile K0
            CPC();
            CPW1();
            __syncthreads();
            char* buf = sm + ((cc & 1) ? OFF_B1 : OFF_B0);
            bf16* Vh = reinterpret_cast<bf16*>(buf);
            bf16* Vl = reinterpret_cast<bf16*>(buf + BUF_LO);
            const int kc = cc - 4;
#pragma unroll
            for (int ks = 0; ks < 2; ks++) {
                wmma::fragment<wmma::matrix_a, 16, 16, 16, bf16, wmma::row_major> ah[2], al[2];
#pragma unroll
                for (int mi = 0; mi < 2; mi++) {
                    wmma::load_matrix_sync(ah[mi], Ph + (wm2 * 32 + mi * 16) * LDP + kc * 32 + ks * 16, LDP);
                    wmma::load_matrix_sync(al[mi], Pl + (wm2 * 32 + mi * 16) * LDP + kc * 32 + ks * 16, LDP);
                }
#pragma unroll
                for (int ei = 0; ei < 2; ei++) {
                    wmma::fragment<wmma::matrix_b, 16, 16, 16, bf16, wmma::row_major> bh, bl;
                    wmma::load_matrix_sync(bh, Vh + ks * 16 * LDA + wn2 * 32 + ei * 16, LDA);
                    wmma::load_matrix_sync(bl, Vl + ks * 16 * LDA + wn2 * 32 + ei * 16, LDA);
#pragma unroll
                    for (int mi = 0; mi < 2; mi++) {
                        wmma::mma_sync(dv[mi][ei], ah[mi], bh, dv[mi][ei]);
                        wmma::mma_sync(dv[mi][ei], ah[mi], bl, dv[mi][ei]);
                        wmma::mma_sync(dv[mi][ei], al[mi], bh, dv[mi][ei]);
                    }
                }
            }
            __syncthreads();
        }
    }

    // ---- outputs ----
#pragma unroll
    for (int mi = 0; mi < 2; mi++)
#pragma unroll
        for (int ei = 0; ei < 2; ei++)
            wmma::store_matrix_sync(
                out_dv + ((size_t)b * NN + n0q + wm2 * 32 + mi * 16) * DD + wn2 * 32 + ei * 16,
                dv[mi][ei], DD, wmma::mem_row_major);
    dsac += __shfl_xor_sync(0xffffffffu, dsac, 1);
    dsac += __shfl_xor_sync(0xffffffffu, dsac, 2);
    dsac += __shfl_xor_sync(0xffffffffu, dsac, 4);
    if ((t & 7) == 0) out_ds[b * NN + n0q + (t >> 3)] = dsac;
}

// ---------------------------------------------------------------------------
extern "C" void kernel_launch(void* const* d_in, const int* in_sizes, int n_in,
                              void* d_out, int out_size) {
    const float* val = nullptr;
    const float* state = nullptr;
    const float* Wv = nullptr;
    for (int i = 0; i < n_in; i++) {
        if (in_sizes[i] == BB * NN * DD) val = (const float*)d_in[i];
        else if (in_sizes[i] == BB * NN) state = (const float*)d_in[i];
        else if (in_sizes[i] == DD * DD) Wv = (const float*)d_in[i];
    }
    float* out    = (float*)d_out;
    float* out_ds = out;
    float* out_dv = out + BB * NN;

    cudaFuncSetAttribute(pv_kernel, cudaFuncAttributeMaxDynamicSharedMemorySize, 202752);
    cudaFuncSetAttribute(prop_kernel, cudaFuncAttributeMaxDynamicSharedMemorySize, 210432);

    split_val<<<BB * NN * DD / 1024, 256>>>(val);
    split_wv<<<DD, 256>>>(Wv);
    pv_kernel<<<BB * NN / 64, 512, 202752>>>();
    prop_kernel<<<BB * (NN / 64), 512, 210432>>>(state, out_ds, out_dv);
}